// round 1
// baseline (speedup 1.0000x reference)
#include <cuda_runtime.h>
#include <math.h>

#define NB 4
#define LQ 128
#define DIM 128
#define HID 512
#define WWIN 5
#define MAXSEG 44
#define MAXINT 384
#define OW (2 + 2*LQ*DIM)   // 32770 floats per batch row

// ---------------- device scratch (no allocations allowed) ----------------
static __device__ float g_enc[NB*LQ*DIM];
static __device__ int   g_nInt[NB];
static __device__ float g_dt[NB*MAXINT];
static __device__ int   g_envSeg[NB*MAXINT];
static __device__ int   g_gsel[NB*LQ];
static __device__ int   g_segS[NB*MAXSEG];
static __device__ int   g_segE[NB*MAXSEG];

// float softplus matching jax.nn.softplus = logaddexp(x, 0)
__device__ __forceinline__ float softplusf(float x){
    return fmaxf(x, 0.f) + log1pf(expf(-fabsf(x)));
}

// disambiguate int-index arrays (values in [0, 2e5)) from float pt (~(1,11] -> bits >= 1e9)
__device__ __forceinline__ bool is_index_arr(const void* p){
    int v = ((const int*)p)[0];
    return (v >= 0 && v < 1000000);
}

// ---------------- kernel 1: encoder (also writes traj_t) ----------------
__global__ void enc_k(const int* __restrict__ hi, const float* __restrict__ emb,
                      const float* __restrict__ w1, const float* __restrict__ b1,
                      const float* __restrict__ w2, const float* __restrict__ b2,
                      float* __restrict__ out)
{
    int l = blockIdx.x, b = blockIdx.y, t = threadIdx.x;
    __shared__ float e[DIM], h[DIM];
    int idx = hi[b*LQ + l];
    e[t] = emb[(size_t)idx*DIM + t];
    __syncthreads();
    float a = b1[t];
#pragma unroll 8
    for (int k = 0; k < DIM; k++) a = fmaf(e[k], w1[k*DIM + t], a);
    h[t] = fmaxf(a, 0.f);
    __syncthreads();
    float a2 = b2[t];
#pragma unroll 8
    for (int k = 0; k < DIM; k++) a2 = fmaf(h[k], w2[k*DIM + t], a2);
    g_enc[(b*LQ + l)*DIM + t] = a2;
    out[(size_t)b*OW + 2 + LQ*DIM + l*DIM + t] = a2;   // traj_t
}

// ---------------- block reduction over 128 threads ----------------
__device__ __forceinline__ float blkRed(float v, int op, float* sb){
#pragma unroll
    for (int o = 16; o > 0; o >>= 1){
        float v2 = __shfl_xor_sync(0xffffffffu, v, o);
        v = op ? fmaxf(v, v2) : (v + v2);
    }
    int w = threadIdx.x >> 5;
    if ((threadIdx.x & 31) == 0) sb[w] = v;
    __syncthreads();
    float r = op ? fmaxf(fmaxf(sb[0], sb[1]), fmaxf(sb[2], sb[3]))
                 : ((sb[0] + sb[1]) + (sb[2] + sb[3]));
    __syncthreads();
    return r;
}

// ---------------- kernel 2: APT partition + time-grid planning ----------------
__global__ void plan_k(const float* __restrict__ ht, const int* __restrict__ hl,
                       const void* __restrict__ p16, const void* __restrict__ p17,
                       const void* __restrict__ p18)
{
    int b = blockIdx.x, t = threadIdx.x;
    // resolve pt among the ambiguous trio
    const float* pt;
    if (is_index_arr(p16)) pt = (const float*)p18;   // order: pos,neg,pt
    else                   pt = (const float*)p16;   // order: pt,pos,neg

    __shared__ double times[LQ];
    __shared__ double bounds[MAXSEG + 2];
    __shared__ int starts[MAXSEG + 1];
    __shared__ float sb[4];
    __shared__ int sj, snb, sns, sm_m, scum;
    __shared__ double ts[LQ + 8];

    int n = hl[b]; if (n > LQ) n = LQ;
    if (t < n) times[t] = (double)ht[b*LQ + t];
    if (t == 0){ sj = 0; snb = 1; sns = 1; bounds[0] = (double)ht[b*LQ]; starts[0] = 0; scum = 0; }
    __syncthreads();

    // sequential change-point scan (all threads iterate together)
    if (n >= 2*WWIN){
        for (;;){
            __syncthreads();
            int j = sj;
            if (j > n - 2*WWIN) break;
            float sL = 0.f, sR = 0.f;
            const float* base = &g_enc[(b*LQ + j)*DIM + t];
#pragma unroll
            for (int r = 0; r < WWIN; r++){ sL += base[r*DIM]; sR += base[(WWIN + r)*DIM]; }
            sL /= (float)WWIN; sR /= (float)WWIN;
            float mL = blkRed(sL, 1, sb);
            float mR = blkRed(sR, 1, sb);
            float eL = expf(sL - mL), eR = expf(sR - mR);
            float suL = blkRed(eL, 0, sb);
            float suR = blkRed(eR, 0, sb);
            float p = eL/suL + 1e-8f;
            float q = eR/suR + 1e-8f;
            float ps = blkRed(p, 0, sb);
            float qs = blkRed(q, 0, sb);
            p /= ps; q /= qs;
            float m  = 0.5f*(p + q);
            float c  = 0.5f*p*logf(p/m) + 0.5f*q*logf(q/m);
            float jsd = blkRed(c, 0, sb);
            if (t == 0){
                if (jsd > 0.5f){
                    bounds[snb] = 0.5*(times[j + WWIN - 1] + times[j + WWIN]);
                    snb++;
                    starts[sns] = j + WWIN; sns++;
                    sj = j + WWIN;
                } else sj = j + 1;
            }
        }
    }
    __syncthreads();
    if (t == 0){
        if (times[n-1] > bounds[snb-1]) { bounds[snb] = times[n-1]; snb++; }
    }
    __syncthreads();

    int nseg = sns, nb2 = snb;
    for (int si = 0; si < nseg; si++){
        int s = starts[si];
        int e = (si + 1 < nseg) ? starts[si+1] - 1 : n - 1;
        if (t == 0){
            g_segS[b*MAXSEG + si] = s; g_segE[b*MAXSEG + si] = e;
            double t0 = bounds[si];
            double t1 = (si + 1 < nb2) ? bounds[si+1] : bounds[nb2-1];
            int m = 0; ts[m++] = t0;
            for (int i = s; i <= e; i++){
                double d = times[i];
                if (d >= t0 && d <= t1 && d != ts[m-1]) ts[m++] = d;
            }
            if (t1 != ts[m-1]) ts[m++] = t1;
            for (int k = 1; k < m; k++)
                if (ts[k] - ts[k-1] < 1e-6) ts[k] = ts[k-1] + 1e-6;
            for (int k = 0; k < m - 1; k++){
                g_dt[b*MAXINT + scum + k] = (float)(ts[k+1] - ts[k]);
                g_envSeg[b*MAXINT + scum + k] = si;
            }
            sm_m = m;
        }
        __syncthreads();
        int m = sm_m, cum = scum;
        for (int i = s + t; i <= e; i += blockDim.x){
            double ti = times[i];
            int best = 0; double bd = fabs(ts[0] - ti);
            for (int k = 1; k < m; k++){
                double dd = fabs(ts[k] - ti);
                if (dd < bd){ bd = dd; best = k; }
            }
            g_gsel[b*LQ + i] = cum + best;
        }
        __syncthreads();
        if (t == 0) scum += m - 1;
        __syncthreads();
    }
    if (t == 0){
        int cum = scum;
        double lb = bounds[nb2-1];
        double ptb = (double)pt[b];
        if (ptb > lb + 1e-6){
            double t1 = ptb;
            if (t1 - lb < 1e-6) t1 = lb + 1e-6;
            g_dt[b*MAXINT + cum] = (float)(t1 - lb);
            g_envSeg[b*MAXINT + cum] = nseg - 1;
            cum++;
        }
        g_nInt[b] = cum;
    }
}

// ---------------- kernel 3: per-batch sequential Euler ODE ----------------
__global__ void __launch_bounds__(512, 1) ode_k(
    const float* __restrict__ usert, const int* __restrict__ u,
    const float* __restrict__ vw1, const float* __restrict__ vb1,
    const float* __restrict__ vw2, const float* __restrict__ vb2,
    const float* __restrict__ vw3, const float* __restrict__ vb3,
    const float* __restrict__ emb, const int* __restrict__ hl,
    const void* __restrict__ p16, const void* __restrict__ p17,
    const void* __restrict__ p18,
    float* __restrict__ out)
{
    int b = blockIdx.x, t = threadIdx.x;
    const int *pos, *neg;
    if (is_index_arr(p16)) { pos = (const int*)p16; neg = (const int*)p17; }
    else                   { pos = (const int*)p17; neg = (const int*)p18; }

    __shared__ float z[DIM], env[DIM], cenv[HID], h1[HID], h2[HID];
    __shared__ float part[16*DIM];     // 8KB scratch (also covers 4*HID)

    int n = hl[b]; if (n > LQ) n = LQ;
    if (t < DIM) z[t] = usert[(size_t)u[b]*DIM + t];
    __syncthreads();

    // state 0 write-out
    if (t < n && g_gsel[b*LQ + t] == 0){
        float* o = &out[(size_t)b*OW + 2 + t*DIM];
        for (int dd = 0; dd < DIM; dd++) o[dd] = z[dd];
    }

    int nInt = g_nInt[b];
    int curSeg = -1;
    for (int j = 0; j < nInt; j++){
        int seg = g_envSeg[b*MAXINT + j];
        if (seg != curSeg){
            curSeg = seg;
            int s = g_segS[b*MAXSEG + seg], e = g_segE[b*MAXSEG + seg];
            __syncthreads();
            if (t < DIM){
                float a = 0.f;
                for (int r = s; r <= e; r++) a += g_enc[(b*LQ + r)*DIM + t];
                env[t] = a / (float)(e - s + 1);
            }
            __syncthreads();
            // fold env half of vf layer-1 into a per-segment constant
            float a = vb1[t];
            for (int k = 0; k < DIM; k++) a = fmaf(env[k], vw1[(DIM + k)*HID + t], a);
            cenv[t] = a;
            __syncthreads();
        }
        float dtsub = 0.5f * g_dt[b*MAXINT + j];   // dt / NSUB, NSUB=2
        for (int sub = 0; sub < 2; sub++){
            // ---- layer 1 (z-half only) ----
            {
                int p = t >> 7, c = t & 127;
                const float* wp = &vw1[(p*32)*HID + 4*c];
                float4 acc = make_float4(0.f, 0.f, 0.f, 0.f);
#pragma unroll 8
                for (int k = 0; k < 32; k++){
                    float4 w = *(const float4*)(wp + k*HID);
                    float zk = z[p*32 + k];
                    acc.x = fmaf(zk, w.x, acc.x); acc.y = fmaf(zk, w.y, acc.y);
                    acc.z = fmaf(zk, w.z, acc.z); acc.w = fmaf(zk, w.w, acc.w);
                }
                *(float4*)&part[p*HID + 4*c] = acc;
            }
            __syncthreads();
            h1[t] = softplusf(cenv[t] + ((part[t] + part[HID + t]) + (part[2*HID + t] + part[3*HID + t])));
            __syncthreads();
            // ---- layer 2 ----
            {
                int p = t >> 7, c = t & 127;
                const float* wp = &vw2[(p*128)*HID + 4*c];
                float4 acc = make_float4(0.f, 0.f, 0.f, 0.f);
#pragma unroll 8
                for (int k = 0; k < 128; k++){
                    float4 w = *(const float4*)(wp + k*HID);
                    float hk = h1[p*128 + k];
                    acc.x = fmaf(hk, w.x, acc.x); acc.y = fmaf(hk, w.y, acc.y);
                    acc.z = fmaf(hk, w.z, acc.z); acc.w = fmaf(hk, w.w, acc.w);
                }
                *(float4*)&part[p*HID + 4*c] = acc;
            }
            __syncthreads();
            h2[t] = softplusf(vb2[t] + ((part[t] + part[HID + t]) + (part[2*HID + t] + part[3*HID + t])));
            __syncthreads();
            // ---- layer 3 ----
            {
                int p = t >> 5, c = t & 31;
                const float* wp = &vw3[(p*32)*DIM + 4*c];
                float4 acc = make_float4(0.f, 0.f, 0.f, 0.f);
#pragma unroll 8
                for (int k = 0; k < 32; k++){
                    float4 w = *(const float4*)(wp + k*DIM);
                    float hk = h2[p*32 + k];
                    acc.x = fmaf(hk, w.x, acc.x); acc.y = fmaf(hk, w.y, acc.y);
                    acc.z = fmaf(hk, w.z, acc.z); acc.w = fmaf(hk, w.w, acc.w);
                }
                *(float4*)&part[p*DIM + 4*c] = acc;
            }
            __syncthreads();
            if (t < DIM){
                float v = vb3[t];
#pragma unroll
                for (int p = 0; p < 16; p++) v += part[p*DIM + t];
                z[t] = z[t] + dtsub * v;
            }
            __syncthreads();
        }
        // write state (j+1) to matching interactions
        int g = j + 1;
        if (t < n && g_gsel[b*LQ + t] == g){
            float* o = &out[(size_t)b*OW + 2 + t*DIM];
            for (int dd = 0; dd < DIM; dd++) o[dd] = z[dd];
        }
    }
    __syncthreads();

    // scores
    float* red = part;
    if (t < DIM) red[t] = z[t] * emb[(size_t)pos[b]*DIM + t];
    __syncthreads();
    for (int s2 = 64; s2 > 0; s2 >>= 1){ if (t < s2) red[t] += red[t + s2]; __syncthreads(); }
    if (t == 0) out[(size_t)b*OW] = red[0];
    __syncthreads();
    if (t < DIM) red[t] = z[t] * emb[(size_t)neg[b]*DIM + t];
    __syncthreads();
    for (int s2 = 64; s2 > 0; s2 >>= 1){ if (t < s2) red[t] += red[t + s2]; __syncthreads(); }
    if (t == 0) out[(size_t)b*OW + 1] = red[0];
}

// ---------------- launch ----------------
extern "C" void kernel_launch(void* const* d_in, const int* in_sizes, int n_in,
                              void* d_out, int out_size)
{
    const float* emb   = (const float*)d_in[0];
    const float* mw1   = (const float*)d_in[1];
    const float* mb1   = (const float*)d_in[2];
    const float* mw2   = (const float*)d_in[3];
    const float* mb2   = (const float*)d_in[4];
    const float* usert = (const float*)d_in[5];
    const float* vw1   = (const float*)d_in[6];
    const float* vb1   = (const float*)d_in[7];
    const float* vw2   = (const float*)d_in[8];
    const float* vb2   = (const float*)d_in[9];
    const float* vw3   = (const float*)d_in[10];
    const float* vb3   = (const float*)d_in[11];
    const int*   u     = (const int*)d_in[12];
    const int*   hi    = (const int*)d_in[13];
    const float* ht    = (const float*)d_in[14];
    const int*   hl    = (const int*)d_in[15];
    // last three may be {pos,neg,pt} (dict order) or {pt,pos,neg} (signature order);
    // resolved on-device by inspecting values.
    const void*  p16   = d_in[16];
    const void*  p17   = d_in[17];
    const void*  p18   = d_in[18];
    float* out = (float*)d_out;

    dim3 ge(LQ, NB);
    enc_k<<<ge, DIM>>>(hi, emb, mw1, mb1, mw2, mb2, out);
    plan_k<<<NB, 128>>>(ht, hl, p16, p17, p18);
    ode_k<<<NB, 512>>>(usert, u, vw1, vb1, vw2, vb2, vw3, vb3, emb, hl,
                       p16, p17, p18, out);
}

// round 3
// speedup vs baseline: 2.6189x; 2.6189x over previous
#include <cuda_runtime.h>
#include <cstdint>
#include <math.h>

#define NB 4
#define LQ 128
#define DIM 128
#define HID 512
#define WWIN 5
#define MAXSEG 44
#define MAXINT 384
#define OW (2 + 2*LQ*DIM)   // 32770 floats per batch row

#define CL 8                // cluster size (CTAs per batch chain)
#define TPB2 256
#define W1P 132             // padded row strides (pad=4 words -> conflict-free)
#define W2P 516
#define W3P 516

// ---------------- device scratch (no allocations allowed) ----------------
static __device__ float g_enc[NB*LQ*DIM];
static __device__ int   g_nInt[NB];
static __device__ float g_dt[NB*MAXINT];
static __device__ int   g_envSeg[NB*MAXINT];
static __device__ int   g_gsel[NB*LQ];
static __device__ int   g_segS[NB*MAXSEG];
static __device__ int   g_segE[NB*MAXSEG];

__device__ __forceinline__ float softplusf(float x){
    return fmaxf(x, 0.f) + log1pf(expf(-fabsf(x)));
}

__device__ __forceinline__ bool is_index_arr(const void* p){
    int v = ((const int*)p)[0];
    return (v >= 0 && v < 1000000);
}

// remote (cluster) smem store
__device__ __forceinline__ void bcast_store(float* lptr, int rank, float v){
    uint32_t la = (uint32_t)__cvta_generic_to_shared(lptr);
    uint32_t ra;
    asm volatile("mapa.shared::cluster.u32 %0, %1, %2;" : "=r"(ra) : "r"(la), "r"(rank));
    asm volatile("st.shared::cluster.f32 [%0], %1;" :: "r"(ra), "f"(v) : "memory");
}

#define CLUSTER_SYNC_() do { \
    asm volatile("barrier.cluster.arrive.aligned;" ::: "memory"); \
    asm volatile("barrier.cluster.wait.aligned;" ::: "memory"); } while(0)

// ---------------- kernel 1: encoder (also writes traj_t) ----------------
__global__ void enc_k(const int* __restrict__ hi, const float* __restrict__ emb,
                      const float* __restrict__ w1, const float* __restrict__ b1,
                      const float* __restrict__ w2, const float* __restrict__ b2,
                      float* __restrict__ out)
{
    int l = blockIdx.x, b = blockIdx.y, t = threadIdx.x;
    __shared__ float e[DIM], h[DIM];
    int idx = hi[b*LQ + l];
    e[t] = emb[(size_t)idx*DIM + t];
    __syncthreads();
    float a = b1[t];
#pragma unroll 8
    for (int k = 0; k < DIM; k++) a = fmaf(e[k], w1[k*DIM + t], a);
    h[t] = fmaxf(a, 0.f);
    __syncthreads();
    float a2 = b2[t];
#pragma unroll 8
    for (int k = 0; k < DIM; k++) a2 = fmaf(h[k], w2[k*DIM + t], a2);
    g_enc[(b*LQ + l)*DIM + t] = a2;
    out[(size_t)b*OW + 2 + LQ*DIM + l*DIM + t] = a2;   // traj_t
}

// ---------------- block reduction over 128 threads ----------------
__device__ __forceinline__ float blkRed(float v, int op, float* sb){
#pragma unroll
    for (int o = 16; o > 0; o >>= 1){
        float v2 = __shfl_xor_sync(0xffffffffu, v, o);
        v = op ? fmaxf(v, v2) : (v + v2);
    }
    int w = threadIdx.x >> 5;
    if ((threadIdx.x & 31) == 0) sb[w] = v;
    __syncthreads();
    float r = op ? fmaxf(fmaxf(sb[0], sb[1]), fmaxf(sb[2], sb[3]))
                 : ((sb[0] + sb[1]) + (sb[2] + sb[3]));
    __syncthreads();
    return r;
}

// ---------------- kernel 2: APT partition + time-grid planning ----------------
__global__ void plan_k(const float* __restrict__ ht, const int* __restrict__ hl,
                       const void* __restrict__ p16, const void* __restrict__ p17,
                       const void* __restrict__ p18)
{
    int b = blockIdx.x, t = threadIdx.x;
    const float* pt;
    if (is_index_arr(p16)) pt = (const float*)p18;   // order: pos,neg,pt
    else                   pt = (const float*)p16;   // order: pt,pos,neg

    __shared__ double times[LQ];
    __shared__ double bounds[MAXSEG + 2];
    __shared__ int starts[MAXSEG + 1];
    __shared__ float sb[4];
    __shared__ int sj, snb, sns, sm_m, scum;
    __shared__ double ts[LQ + 8];

    int n = hl[b]; if (n > LQ) n = LQ;
    if (t < n) times[t] = (double)ht[b*LQ + t];
    if (t == 0){ sj = 0; snb = 1; sns = 1; bounds[0] = (double)ht[b*LQ]; starts[0] = 0; scum = 0; }
    __syncthreads();

    if (n >= 2*WWIN){
        for (;;){
            __syncthreads();
            int j = sj;
            if (j > n - 2*WWIN) break;
            float sL = 0.f, sR = 0.f;
            const float* base = &g_enc[(b*LQ + j)*DIM + t];
#pragma unroll
            for (int r = 0; r < WWIN; r++){ sL += base[r*DIM]; sR += base[(WWIN + r)*DIM]; }
            sL /= (float)WWIN; sR /= (float)WWIN;
            float mL = blkRed(sL, 1, sb);
            float mR = blkRed(sR, 1, sb);
            float eL = expf(sL - mL), eR = expf(sR - mR);
            float suL = blkRed(eL, 0, sb);
            float suR = blkRed(eR, 0, sb);
            float p = eL/suL + 1e-8f;
            float q = eR/suR + 1e-8f;
            float ps = blkRed(p, 0, sb);
            float qs = blkRed(q, 0, sb);
            p /= ps; q /= qs;
            float m  = 0.5f*(p + q);
            float c  = 0.5f*p*logf(p/m) + 0.5f*q*logf(q/m);
            float jsd = blkRed(c, 0, sb);
            if (t == 0){
                if (jsd > 0.5f){
                    bounds[snb] = 0.5*(times[j + WWIN - 1] + times[j + WWIN]);
                    snb++;
                    starts[sns] = j + WWIN; sns++;
                    sj = j + WWIN;
                } else sj = j + 1;
            }
        }
    }
    __syncthreads();
    if (t == 0){
        if (times[n-1] > bounds[snb-1]) { bounds[snb] = times[n-1]; snb++; }
    }
    __syncthreads();

    int nseg = sns, nb2 = snb;
    for (int si = 0; si < nseg; si++){
        int s = starts[si];
        int e = (si + 1 < nseg) ? starts[si+1] - 1 : n - 1;
        if (t == 0){
            g_segS[b*MAXSEG + si] = s; g_segE[b*MAXSEG + si] = e;
            double t0 = bounds[si];
            double t1 = (si + 1 < nb2) ? bounds[si+1] : bounds[nb2-1];
            int m = 0; ts[m++] = t0;
            for (int i = s; i <= e; i++){
                double d = times[i];
                if (d >= t0 && d <= t1 && d != ts[m-1]) ts[m++] = d;
            }
            if (t1 != ts[m-1]) ts[m++] = t1;
            for (int k = 1; k < m; k++)
                if (ts[k] - ts[k-1] < 1e-6) ts[k] = ts[k-1] + 1e-6;
            for (int k = 0; k < m - 1; k++){
                g_dt[b*MAXINT + scum + k] = (float)(ts[k+1] - ts[k]);
                g_envSeg[b*MAXINT + scum + k] = si;
            }
            sm_m = m;
        }
        __syncthreads();
        int m = sm_m, cum = scum;
        for (int i = s + t; i <= e; i += blockDim.x){
            double ti = times[i];
            int best = 0; double bd = fabs(ts[0] - ti);
            for (int k = 1; k < m; k++){
                double dd = fabs(ts[k] - ti);
                if (dd < bd){ bd = dd; best = k; }
            }
            g_gsel[b*LQ + i] = cum + best;
        }
        __syncthreads();
        if (t == 0) scum += m - 1;
        __syncthreads();
    }
    if (t == 0){
        int cum = scum;
        double lb = bounds[nb2-1];
        double ptb = (double)pt[b];
        if (ptb > lb + 1e-6){
            double t1 = ptb;
            if (t1 - lb < 1e-6) t1 = lb + 1e-6;
            g_dt[b*MAXINT + cum] = (float)(t1 - lb);
            g_envSeg[b*MAXINT + cum] = nseg - 1;
            cum++;
        }
        g_nInt[b] = cum;
    }
}

// ---------------- kernel 3: clustered Euler ODE ----------------
struct OdeSmem {
    float w1t[64*W1P];      // layer1 z-half, transposed [o][k] padded
    float w2t[64*W2P];      // layer2 transposed
    float w3t[16*W3P];      // layer3 transposed
    float z[DIM];
    float h1[HID];
    float h2[HID];
    float cenv[64];
    float b2s[64];
    float b3s[16];
    float part[16*64];
    float env[DIM];
    float dtv[MAXINT];
    int   eseg[MAXINT];
    int   segS[MAXSEG];
    int   segE[MAXSEG];
    int   gsel[LQ];
};

extern __shared__ char ode_raw[];

__global__ void __launch_bounds__(TPB2, 1) __cluster_dims__(CL, 1, 1)
ode_cl_k(const float* __restrict__ usert, const int* __restrict__ u,
         const float* __restrict__ vw1, const float* __restrict__ vb1,
         const float* __restrict__ vw2, const float* __restrict__ vb2,
         const float* __restrict__ vw3, const float* __restrict__ vb3,
         const float* __restrict__ emb, const int* __restrict__ hl,
         const void* __restrict__ p16, const void* __restrict__ p17,
         const void* __restrict__ p18,
         float* __restrict__ out)
{
    OdeSmem* S = (OdeSmem*)ode_raw;
    int t = threadIdx.x;
    uint32_t cr; asm("mov.u32 %0, %%cluster_ctarank;" : "=r"(cr));
    int b = blockIdx.x / CL;

    const int *pos, *neg;
    if (is_index_arr(p16)) { pos = (const int*)p16; neg = (const int*)p17; }
    else                   { pos = (const int*)p17; neg = (const int*)p18; }

    // ---- init: weights -> smem (transposed, padded) ----
    for (int idx = t; idx < 64*128; idx += TPB2){
        int k = idx >> 6, o = idx & 63;
        S->w1t[o*W1P + k] = vw1[k*HID + cr*64 + o];
    }
    for (int idx = t; idx < 64*512; idx += TPB2){
        int k = idx >> 6, o = idx & 63;
        S->w2t[o*W2P + k] = vw2[k*HID + cr*64 + o];
    }
    for (int idx = t; idx < 16*512; idx += TPB2){
        int k = idx >> 4, o = idx & 15;
        S->w3t[o*W3P + k] = vw3[k*DIM + cr*16 + o];
    }
    if (t < 64) S->b2s[t] = vb2[cr*64 + t];
    if (t < 16) S->b3s[t] = vb3[cr*16 + t];
    for (int i = t; i < MAXINT; i += TPB2){
        S->dtv[i] = g_dt[b*MAXINT + i];
        S->eseg[i] = g_envSeg[b*MAXINT + i];
    }
    for (int i = t; i < MAXSEG; i += TPB2){
        S->segS[i] = g_segS[b*MAXSEG + i];
        S->segE[i] = g_segE[b*MAXSEG + i];
    }
    for (int i = t; i < LQ; i += TPB2) S->gsel[i] = g_gsel[b*LQ + i];
    if (t < DIM) S->z[t] = usert[(size_t)u[b]*DIM + t];
    __syncthreads();

    int n = hl[b]; if (n > LQ) n = LQ;

    // initial (grid 0) state writes
    {
        int o = t & 15, ib = t >> 4;
#pragma unroll
        for (int pass = 0; pass < 8; pass++){
            int i = pass*16 + ib;
            if (i < n && S->gsel[i] == 0)
                out[(size_t)b*OW + 2 + i*DIM + cr*16 + o] = S->z[cr*16 + o];
        }
    }

    int nInt = g_nInt[b];
    int curSeg = -1;
    for (int j = 0; j < nInt; j++){
        int seg = S->eseg[j];
        if (seg != curSeg){
            curSeg = seg;
            int s = S->segS[seg], e = S->segE[seg];
            __syncthreads();
            if (t < DIM){
                float a = 0.f;
                for (int r2 = s; r2 <= e; r2++) a += g_enc[(b*LQ + r2)*DIM + t];
                S->env[t] = a / (float)(e - s + 1);
            }
            __syncthreads();
            {   // cenv = vb1 + env-half of W1 (from global, rare)
                int o = t & 63, p = t >> 6;
                float acc = 0.f;
                const float* wp = &vw1[(DIM + p*32)*HID + cr*64 + o];
                const float* ep = &S->env[p*32];
#pragma unroll 8
                for (int kk = 0; kk < 32; kk++)
                    acc = fmaf(ep[kk], wp[kk*HID], acc);
                S->part[p*64 + o] = acc;
            }
            __syncthreads();
            if (t < 64)
                S->cenv[t] = vb1[cr*64 + t] +
                    ((S->part[t] + S->part[64 + t]) + (S->part[128 + t] + S->part[192 + t]));
            __syncthreads();
        }
        float dtsub = 0.5f * S->dtv[j];   // dt / NSUB, NSUB=2
        for (int sub = 0; sub < 2; sub++){
            // ---------- layer 1: 64 out x 128 k ----------
            {
                int o = t & 63, p = t >> 6;      // 4 parts x 32 k
                const float* wr = &S->w1t[o*W1P + p*32];
                const float* zr = &S->z[p*32];
                float4 a4 = make_float4(0.f,0.f,0.f,0.f);
#pragma unroll
                for (int kk = 0; kk < 8; kk++){
                    float4 w = *(const float4*)(wr + kk*4);
                    float4 x = *(const float4*)(zr + kk*4);
                    a4.x = fmaf(w.x, x.x, a4.x); a4.y = fmaf(w.y, x.y, a4.y);
                    a4.z = fmaf(w.z, x.z, a4.z); a4.w = fmaf(w.w, x.w, a4.w);
                }
                S->part[p*64 + o] = (a4.x + a4.y) + (a4.z + a4.w);
            }
            __syncthreads();
            if (t < 64){
                float v = S->cenv[t] +
                    ((S->part[t] + S->part[64 + t]) + (S->part[128 + t] + S->part[192 + t]));
                S->h1[cr*64 + t] = softplusf(v);
            }
            __syncthreads();
            {   // broadcast h1 slice to all ranks (2 stores per thread)
                int o = t & 63, d0 = t >> 6;
                float v = S->h1[cr*64 + o];
                bcast_store(&S->h1[cr*64 + o], d0, v);
                bcast_store(&S->h1[cr*64 + o], d0 + 4, v);
            }
            CLUSTER_SYNC_();
            // ---------- layer 2: 64 out x 512 k ----------
            {
                int o = t & 63, p = t >> 6;      // 4 parts x 128 k
                const float* wr = &S->w2t[o*W2P + p*128];
                const float* hr = &S->h1[p*128];
                float4 a4 = make_float4(0.f,0.f,0.f,0.f);
#pragma unroll 8
                for (int kk = 0; kk < 32; kk++){
                    float4 w = *(const float4*)(wr + kk*4);
                    float4 x = *(const float4*)(hr + kk*4);
                    a4.x = fmaf(w.x, x.x, a4.x); a4.y = fmaf(w.y, x.y, a4.y);
                    a4.z = fmaf(w.z, x.z, a4.z); a4.w = fmaf(w.w, x.w, a4.w);
                }
                S->part[p*64 + o] = (a4.x + a4.y) + (a4.z + a4.w);
            }
            __syncthreads();
            if (t < 64){
                float v = S->b2s[t] +
                    ((S->part[t] + S->part[64 + t]) + (S->part[128 + t] + S->part[192 + t]));
                S->h2[cr*64 + t] = softplusf(v);
            }
            __syncthreads();
            {
                int o = t & 63, d0 = t >> 6;
                float v = S->h2[cr*64 + o];
                bcast_store(&S->h2[cr*64 + o], d0, v);
                bcast_store(&S->h2[cr*64 + o], d0 + 4, v);
            }
            CLUSTER_SYNC_();
            // ---------- layer 3: 16 out x 512 k ----------
            {
                int o = t & 15, p = t >> 4;      // 16 parts x 32 k
                const float* wr = &S->w3t[o*W3P + p*32];
                const float* hr = &S->h2[p*32];
                float4 a4 = make_float4(0.f,0.f,0.f,0.f);
#pragma unroll
                for (int kk = 0; kk < 8; kk++){
                    float4 w = *(const float4*)(wr + kk*4);
                    float4 x = *(const float4*)(hr + kk*4);
                    a4.x = fmaf(w.x, x.x, a4.x); a4.y = fmaf(w.y, x.y, a4.y);
                    a4.z = fmaf(w.z, x.z, a4.z); a4.w = fmaf(w.w, x.w, a4.w);
                }
                S->part[p*16 + o] = (a4.x + a4.y) + (a4.z + a4.w);
            }
            __syncthreads();
            if (t < 16){
                float dv = S->b3s[t];
#pragma unroll
                for (int q = 0; q < 16; q++) dv += S->part[q*16 + t];
                S->z[cr*16 + t] = S->z[cr*16 + t] + dtsub * dv;
            }
            __syncthreads();
            if (t < 128){   // broadcast z slice (1 store per thread, 8 ranks)
                int o = t & 15, d = t >> 4;
                float v = S->z[cr*16 + o];
                bcast_store(&S->z[cr*16 + o], d, v);
            }
            CLUSTER_SYNC_();
        }
        // write interaction states matched to grid point j+1
        {
            int o = t & 15, ib = t >> 4, g = j + 1;
#pragma unroll
            for (int pass = 0; pass < 8; pass++){
                int i = pass*16 + ib;
                if (i < n && S->gsel[i] == g)
                    out[(size_t)b*OW + 2 + i*DIM + cr*16 + o] = S->z[cr*16 + o];
            }
        }
    }

    // scores: rank 0 -> pos, rank 1 -> neg
    __syncthreads();
    if (cr < 2){
        const int* pn = (cr == 0) ? pos : neg;
        float v = (t < DIM) ? S->z[t] * emb[(size_t)pn[b]*DIM + t] : 0.f;
#pragma unroll
        for (int o2 = 16; o2 > 0; o2 >>= 1) v += __shfl_xor_sync(0xffffffffu, v, o2);
        if ((t & 31) == 0) S->part[t >> 5] = v;
        __syncthreads();
        if (t == 0){
            float s = 0.f;
            for (int w = 0; w < TPB2/32; w++) s += S->part[w];
            out[(size_t)b*OW + cr] = s;
        }
    }
}

// ---------------- launch ----------------
extern "C" void kernel_launch(void* const* d_in, const int* in_sizes, int n_in,
                              void* d_out, int out_size)
{
    const float* emb   = (const float*)d_in[0];
    const float* mw1   = (const float*)d_in[1];
    const float* mb1   = (const float*)d_in[2];
    const float* mw2   = (const float*)d_in[3];
    const float* mb2   = (const float*)d_in[4];
    const float* usert = (const float*)d_in[5];
    const float* vw1   = (const float*)d_in[6];
    const float* vb1   = (const float*)d_in[7];
    const float* vw2   = (const float*)d_in[8];
    const float* vb2   = (const float*)d_in[9];
    const float* vw3   = (const float*)d_in[10];
    const float* vb3   = (const float*)d_in[11];
    const int*   u     = (const int*)d_in[12];
    const int*   hi    = (const int*)d_in[13];
    const float* ht    = (const float*)d_in[14];
    const int*   hl    = (const int*)d_in[15];
    const void*  p16   = d_in[16];
    const void*  p17   = d_in[17];
    const void*  p18   = d_in[18];
    float* out = (float*)d_out;

    static int smem_set = 0;
    if (!smem_set){
        cudaFuncSetAttribute(ode_cl_k, cudaFuncAttributeMaxDynamicSharedMemorySize,
                             (int)sizeof(OdeSmem));
        smem_set = 1;
    }

    dim3 ge(LQ, NB);
    enc_k<<<ge, DIM>>>(hi, emb, mw1, mb1, mw2, mb2, out);
    plan_k<<<NB, 128>>>(ht, hl, p16, p17, p18);
    ode_cl_k<<<NB*CL, TPB2, sizeof(OdeSmem)>>>(usert, u, vw1, vb1, vw2, vb2, vw3, vb3,
                                               emb, hl, p16, p17, p18, out);
}